// round 11
// baseline (speedup 1.0000x reference)
#include <cuda_runtime.h>

// Fused Quanvolution-Hybrid (analytic 4-qubit circuit), f32x2, G=6 @ 5 blocks/SM.
//   theta_w = conv_out_w + angles[w];  c_w=cos, s_w=sin
//   <Z0> = cos(a4)*c0 - sin(a4)*s0*s1
//   <Z1> = c0*c1,  <Z2> = c0*c1*c2,  <Z3> = c0*c1*c2*c3
// Patches 0..191 -> threads 1:1. Patches 192..195 x 6 images -> lanes 0..23 of warp 0.

#define G_IMGS 6
#define TPB    192        // 6 warps, all fully active
#define NW     6
#define NP     5          // 10 classes as 5 packed pairs
#define PSTR   31         // 6*5 + 1 pad (odd -> conflict-free-ish strides)

typedef unsigned long long u64;

__device__ __forceinline__ u64 pack2(float lo, float hi) {
    u64 r; asm("mov.b64 %0,{%1,%2};" : "=l"(r) : "f"(lo), "f"(hi)); return r;
}
__device__ __forceinline__ void unpack2(u64 v, float& lo, float& hi) {
    asm("mov.b64 {%0,%1},%2;" : "=f"(lo), "=f"(hi) : "l"(v));
}
__device__ __forceinline__ u64 fma2(u64 a, u64 b, u64 c) {
    u64 d; asm("fma.rn.f32x2 %0,%1,%2,%3;" : "=l"(d) : "l"(a), "l"(b), "l"(c)); return d;
}
__device__ __forceinline__ u64 add2(u64 a, u64 b) {
    u64 d; asm("add.rn.f32x2 %0,%1,%2;" : "=l"(d) : "l"(a), "l"(b)); return d;
}

__global__ __launch_bounds__(TPB, 5) void quanv_fused(
    const float* __restrict__ x,        // [B,1,28,28]
    const float* __restrict__ conv_w,   // [4,1,2,2]
    const float* __restrict__ conv_b,   // [4]
    const float* __restrict__ angles,   // [5]
    const float* __restrict__ fc_w,     // [10, 784]
    const float* __restrict__ fc_b,     // [10]
    float* __restrict__ out,            // [B,10]
    int B)
{
    const int t    = threadIdx.x;
    const int lane = t & 31;
    const int warp = t >> 5;
    const int b0   = blockIdx.x * G_IMGS;

    __shared__ u64   s_part[NW][16][PSTR];     // main partial logit pairs (23.8 KB)
    __shared__ u64   s_extra[G_IMGS][4][NP];   // warp-0 epilogue partials
    __shared__ u64   s_fwx[4][4][NP];          // fc weights for patches 192..195 (warp-0 private)
    __shared__ float s_logits[G_IMGS][10];

    const int h    = t / 14;
    const int wq   = t - h * 14;
    const int poff = (2 * h) * 28 + 2 * wq;   // even -> 8B aligned float2

    // ---- 1) issue half-0 x loads first (3 images) ----
    float2 p0[3], p1[3];
#pragma unroll
    for (int gg = 0; gg < 3; gg++) {
        const int b = b0 + gg;
        if (b < B) {
            const float* xb = x + (size_t)b * 784 + poff;
            p0[gg] = *reinterpret_cast<const float2*>(xb);
            p1[gg] = *reinterpret_cast<const float2*>(xb + 28);
        } else {
            p0[gg] = make_float2(0.f, 0.f);
            p1[gg] = make_float2(0.f, 0.f);
        }
    }

    // ---- 2) uniform parameters; conv weights packed per channel pair ----
    u64 wA[2], wB[2], wC[2], wD[2], bbp[2];
#pragma unroll
    for (int c2 = 0; c2 < 2; c2++) {
        const int ca = 2 * c2, cb = 2 * c2 + 1;
        wA[c2]  = pack2(conv_w[ca * 4 + 0], conv_w[cb * 4 + 0]);
        wB[c2]  = pack2(conv_w[ca * 4 + 1], conv_w[cb * 4 + 1]);
        wC[c2]  = pack2(conv_w[ca * 4 + 2], conv_w[cb * 4 + 2]);
        wD[c2]  = pack2(conv_w[ca * 4 + 3], conv_w[cb * 4 + 3]);
        bbp[c2] = pack2(conv_b[ca] + angles[ca], conv_b[cb] + angles[cb]);
    }
    float sa4, ca4;
    __sincosf(angles[4], &sa4, &ca4);

    // ---- 3) per-thread FC weight slice (patch t), packed class pairs (L2-resident) ----
    u64 fw2[4][NP];
#pragma unroll
    for (int c = 0; c < 4; c++) {
#pragma unroll
        for (int j = 0; j < NP; j++) {
            float lo = fc_w[(2 * j)     * 784 + c * 196 + t];
            float hi = fc_w[(2 * j + 1) * 784 + c * 196 + t];
            fw2[c][j] = pack2(lo, hi);
        }
    }

    // extra-patch FC weights -> shared, warp 0 only (race-free)
    if (warp == 0) {
        for (int r = lane; r < 80; r += 32) {
            const int c  = r / 20;
            const int rr = r - c * 20;
            const int ee = rr / NP;
            const int j  = rr - ee * NP;
            const int pe = 192 + ee;
            s_fwx[c][ee][j] = pack2(fc_w[(2 * j) * 784 + c * 196 + pe],
                                    fc_w[(2 * j + 1) * 784 + c * 196 + pe]);
        }
    }

    const u64 zz = pack2(0.0f, 0.0f);

    // ---- 4) main loop: two halves of 3 images ----
#pragma unroll
    for (int half = 0; half < 2; half++) {
        if (half == 1) {
#pragma unroll
            for (int gg = 0; gg < 3; gg++) {
                const int b = b0 + 3 + gg;
                if (b < B) {
                    const float* xb = x + (size_t)b * 784 + poff;
                    p0[gg] = *reinterpret_cast<const float2*>(xb);
                    p1[gg] = *reinterpret_cast<const float2*>(xb + 28);
                } else {
                    p0[gg] = make_float2(0.f, 0.f);
                    p1[gg] = make_float2(0.f, 0.f);
                }
            }
        }

#pragma unroll
        for (int gg = 0; gg < 3; gg++) {
            const int g = half * 3 + gg;

            // packed conv: theta pairs (ch 0,1) and (ch 2,3)
            const u64 px = pack2(p0[gg].x, p0[gg].x);
            const u64 py = pack2(p0[gg].y, p0[gg].y);
            const u64 pz = pack2(p1[gg].x, p1[gg].x);
            const u64 pw = pack2(p1[gg].y, p1[gg].y);

            float th0, th1, th2, th3;
            {
                u64 tp0 = fma2(px, wA[0], fma2(py, wB[0], fma2(pz, wC[0], fma2(pw, wD[0], bbp[0]))));
                u64 tp1 = fma2(px, wA[1], fma2(py, wB[1], fma2(pz, wC[1], fma2(pw, wD[1], bbp[1]))));
                unpack2(tp0, th0, th1);
                unpack2(tp1, th2, th3);
            }

            float s0, c0, s1, c1;
            __sincosf(th0, &s0, &c0);
            __sincosf(th1, &s1, &c1);
            const float c2 = __cosf(th2);
            const float c3 = __cosf(th3);

            const float okf = (b0 + g < B) ? 1.0f : 0.0f;
            const float ez0 = okf * fmaf(ca4, c0, -sa4 * s0 * s1);
            const float ez1 = okf * (c0 * c1);
            const float ez2 = ez1 * c2;
            const float ez3 = ez2 * c3;

            const u64 e0 = pack2(ez0, ez0);
            const u64 e1 = pack2(ez1, ez1);
            const u64 e2 = pack2(ez2, ez2);
            const u64 e3 = pack2(ez3, ez3);

            u64 acc[NP];
#pragma unroll
            for (int j = 0; j < NP; j++)
                acc[j] = fma2(e0, fw2[0][j],
                         fma2(e1, fw2[1][j],
                         fma2(e2, fw2[2][j],
                         fma2(e3, fw2[3][j], zz))));

            // 1-level reduce (lane += lane+16), packed
#pragma unroll
            for (int j = 0; j < NP; j++) {
                u64 other = __shfl_down_sync(0xffffffffu, acc[j], 16);
                acc[j] = add2(acc[j], other);
            }
            if (lane < 16) {
#pragma unroll
                for (int j = 0; j < NP; j++)
                    s_part[warp][lane][g * NP + j] = acc[j];
            }
        }
    }

    // ---- 5) warp-0 epilogue: patches 192..195 x 6 images -> lanes 0..23 ----
    if (warp == 0) {
        __syncwarp();                   // s_fwx cross-lane visibility
        const int e  = lane & 3;        // extra patch 192+e -> (h=13, w=10+e)
        const int ge = lane >> 2;       // image index 0..7 (only <6 active)
        const int b  = b0 + ge;
        if (ge < G_IMGS) {
            u64 accx[NP];
            if (b < B) {
                const float* xb = x + (size_t)b * 784 + 26 * 28 + 2 * (10 + e);
                float2 q0 = *reinterpret_cast<const float2*>(xb);
                float2 q1 = *reinterpret_cast<const float2*>(xb + 28);

                const u64 px = pack2(q0.x, q0.x);
                const u64 py = pack2(q0.y, q0.y);
                const u64 pz = pack2(q1.x, q1.x);
                const u64 pw = pack2(q1.y, q1.y);

                float th0, th1, th2, th3;
                {
                    u64 tp0 = fma2(px, wA[0], fma2(py, wB[0], fma2(pz, wC[0], fma2(pw, wD[0], bbp[0]))));
                    u64 tp1 = fma2(px, wA[1], fma2(py, wB[1], fma2(pz, wC[1], fma2(pw, wD[1], bbp[1]))));
                    unpack2(tp0, th0, th1);
                    unpack2(tp1, th2, th3);
                }

                float s0, c0, s1, c1;
                __sincosf(th0, &s0, &c0);
                __sincosf(th1, &s1, &c1);
                const float c2 = __cosf(th2);
                const float c3 = __cosf(th3);

                const float ez0 = fmaf(ca4, c0, -sa4 * s0 * s1);
                const float ez1 = c0 * c1;
                const float ez2 = ez1 * c2;
                const float ez3 = ez2 * c3;

                const u64 e0p = pack2(ez0, ez0);
                const u64 e1p = pack2(ez1, ez1);
                const u64 e2p = pack2(ez2, ez2);
                const u64 e3p = pack2(ez3, ez3);
#pragma unroll
                for (int j = 0; j < NP; j++)
                    accx[j] = fma2(e0p, s_fwx[0][e][j],
                              fma2(e1p, s_fwx[1][e][j],
                              fma2(e2p, s_fwx[2][e][j],
                              fma2(e3p, s_fwx[3][e][j], zz))));
            } else {
#pragma unroll
                for (int j = 0; j < NP; j++) accx[j] = zz;
            }
#pragma unroll
            for (int j = 0; j < NP; j++)
                s_extra[ge][e][j] = accx[j];
        }
    }
    __syncthreads();

    // ---- 6) tail: one thread per (image, class-pair) sums 96 partials + extras ----
    if (t < G_IMGS * NP) {
        const int g = t / NP, j = t - g * NP;
        u64 v0 = pack2(fc_b[2 * j], fc_b[2 * j + 1]);
        u64 v1 = zz, v2 = zz, v3 = zz;
#pragma unroll
        for (int k = 0; k < NW; k++) {
#pragma unroll
            for (int i = 0; i < 16; i += 4) {
                v0 = add2(v0, s_part[k][i + 0][t]);
                v1 = add2(v1, s_part[k][i + 1][t]);
                v2 = add2(v2, s_part[k][i + 2][t]);
                v3 = add2(v3, s_part[k][i + 3][t]);
            }
        }
#pragma unroll
        for (int ee = 0; ee < 4; ee++)
            v0 = add2(v0, s_extra[g][ee][j]);
        u64 v = add2(add2(v0, v1), add2(v2, v3));
        float lo, hi; unpack2(v, lo, hi);
        s_logits[g][2 * j]     = lo;
        s_logits[g][2 * j + 1] = hi;
    }
    __syncthreads();

    // ---- 7) log_softmax over 10 classes ----
    if (t < G_IMGS * 10) {
        const int g = t / 10, o = t - g * 10;
        const int b = b0 + g;
        if (b < B) {
            float m = -1e30f;
#pragma unroll
            for (int j = 0; j < 10; j++) m = fmaxf(m, s_logits[g][j]);
            float se = 0.0f;
#pragma unroll
            for (int j = 0; j < 10; j++) se += __expf(s_logits[g][j] - m);
            out[b * 10 + o] = s_logits[g][o] - m - __logf(se);
        }
    }
}

extern "C" void kernel_launch(void* const* d_in, const int* in_sizes, int n_in,
                              void* d_out, int out_size)
{
    const float* x      = (const float*)d_in[0];
    const float* conv_w = (const float*)d_in[1];
    const float* conv_b = (const float*)d_in[2];
    const float* angles = (const float*)d_in[3];
    const float* fc_w   = (const float*)d_in[4];
    const float* fc_b   = (const float*)d_in[5];
    float* out = (float*)d_out;

    const int B = in_sizes[0] / 784;                 // 4096
    const int blocks = (B + G_IMGS - 1) / G_IMGS;    // 683

    quanv_fused<<<blocks, TPB>>>(x, conv_w, conv_b, angles, fc_w, fc_b, out, B);
}

// round 12
// speedup vs baseline: 1.2149x; 1.2149x over previous
#include <cuda_runtime.h>

// Fused Quanvolution-Hybrid (analytic 4-qubit circuit), f32x2, G=7 balanced grid.
//   theta_w = conv_out_w + angles[w];  c_w=cos, s_w=sin
//   <Z0> = cos(a4)*c0 - sin(a4)*s0*s1
//   <Z1> = c0*c1,  <Z2> = c0*c1*c2,  <Z3> = c0*c1*c2*c3
// Patches 0..191 -> threads 1:1. Patches 192..195 x 7 images -> lanes 0..27 of warp 0.

#define G_IMGS 7
#define TPB    192        // 6 warps, all fully active
#define NW     6
#define NP     5          // 10 classes as 5 packed pairs
#define PSTR   37         // 7*5 + 2 pad (odd stride -> conflict-free)

typedef unsigned long long u64;

__device__ __forceinline__ u64 pack2(float lo, float hi) {
    u64 r; asm("mov.b64 %0,{%1,%2};" : "=l"(r) : "f"(lo), "f"(hi)); return r;
}
__device__ __forceinline__ void unpack2(u64 v, float& lo, float& hi) {
    asm("mov.b64 {%0,%1},%2;" : "=f"(lo), "=f"(hi) : "l"(v));
}
__device__ __forceinline__ u64 fma2(u64 a, u64 b, u64 c) {
    u64 d; asm("fma.rn.f32x2 %0,%1,%2,%3;" : "=l"(d) : "l"(a), "l"(b), "l"(c)); return d;
}
__device__ __forceinline__ u64 add2(u64 a, u64 b) {
    u64 d; asm("add.rn.f32x2 %0,%1,%2;" : "=l"(d) : "l"(a), "l"(b)); return d;
}

__global__ __launch_bounds__(TPB, 4) void quanv_fused(
    const float* __restrict__ x,        // [B,1,28,28]
    const float* __restrict__ conv_w,   // [4,1,2,2]
    const float* __restrict__ conv_b,   // [4]
    const float* __restrict__ angles,   // [5]
    const float* __restrict__ fc_w,     // [10, 784]
    const float* __restrict__ fc_b,     // [10]
    float* __restrict__ out,            // [B,10]
    int B)
{
    const int t    = threadIdx.x;
    const int lane = t & 31;
    const int warp = t >> 5;
    const int b0   = blockIdx.x * G_IMGS;

    __shared__ u64   s_part[NW][16][PSTR];     // main partial logit pairs (~28 KB)
    __shared__ u64   s_extra[G_IMGS][4][NP];   // warp-0 epilogue partials
    __shared__ u64   s_fwx[4][4][NP];          // fc weights for patches 192..195 (warp-0 private)
    __shared__ float s_logits[G_IMGS][10];

    const int h    = t / 14;
    const int wq   = t - h * 14;
    const int poff = (2 * h) * 28 + 2 * wq;   // even -> 8B aligned float2

    // ---- 1) issue half-0 x loads first (4 images; DRAM latency starts draining) ----
    float2 p0[4], p1[4];
#pragma unroll
    for (int gg = 0; gg < 4; gg++) {
        const int b = b0 + gg;
        if (b < B) {
            const float* xb = x + (size_t)b * 784 + poff;
            p0[gg] = *reinterpret_cast<const float2*>(xb);
            p1[gg] = *reinterpret_cast<const float2*>(xb + 28);
        } else {
            p0[gg] = make_float2(0.f, 0.f);
            p1[gg] = make_float2(0.f, 0.f);
        }
    }

    // ---- 2) uniform parameters; conv weights packed per channel pair ----
    u64 wA[2], wB[2], wC[2], wD[2], bbp[2];
#pragma unroll
    for (int c2 = 0; c2 < 2; c2++) {
        const int ca = 2 * c2, cb = 2 * c2 + 1;
        wA[c2]  = pack2(conv_w[ca * 4 + 0], conv_w[cb * 4 + 0]);
        wB[c2]  = pack2(conv_w[ca * 4 + 1], conv_w[cb * 4 + 1]);
        wC[c2]  = pack2(conv_w[ca * 4 + 2], conv_w[cb * 4 + 2]);
        wD[c2]  = pack2(conv_w[ca * 4 + 3], conv_w[cb * 4 + 3]);
        bbp[c2] = pack2(conv_b[ca] + angles[ca], conv_b[cb] + angles[cb]);
    }
    float sa4, ca4;
    __sincosf(angles[4], &sa4, &ca4);

    // ---- 3) per-thread FC weight slice (patch t), packed class pairs (L2-resident) ----
    u64 fw2[4][NP];
#pragma unroll
    for (int c = 0; c < 4; c++) {
#pragma unroll
        for (int j = 0; j < NP; j++) {
            float lo = fc_w[(2 * j)     * 784 + c * 196 + t];
            float hi = fc_w[(2 * j + 1) * 784 + c * 196 + t];
            fw2[c][j] = pack2(lo, hi);
        }
    }

    // extra-patch FC weights -> shared, warp 0 only (race-free)
    if (warp == 0) {
        for (int r = lane; r < 80; r += 32) {
            const int c  = r / 20;
            const int rr = r - c * 20;
            const int ee = rr / NP;
            const int j  = rr - ee * NP;
            const int pe = 192 + ee;
            s_fwx[c][ee][j] = pack2(fc_w[(2 * j) * 784 + c * 196 + pe],
                                    fc_w[(2 * j + 1) * 784 + c * 196 + pe]);
        }
    }

    const u64 zz = pack2(0.0f, 0.0f);

    // ---- 4) main loop: half 0 = 4 images, half 1 = 3 images ----
#pragma unroll
    for (int half = 0; half < 2; half++) {
        const int hn = (half == 0) ? 4 : 3;
        if (half == 1) {
#pragma unroll
            for (int gg = 0; gg < 3; gg++) {
                const int b = b0 + 4 + gg;
                if (b < B) {
                    const float* xb = x + (size_t)b * 784 + poff;
                    p0[gg] = *reinterpret_cast<const float2*>(xb);
                    p1[gg] = *reinterpret_cast<const float2*>(xb + 28);
                } else {
                    p0[gg] = make_float2(0.f, 0.f);
                    p1[gg] = make_float2(0.f, 0.f);
                }
            }
        }

#pragma unroll
        for (int gg = 0; gg < 4; gg++) {
            if (gg >= hn) break;
            const int g = half * 4 + gg;

            // packed conv: theta pairs (ch 0,1) and (ch 2,3)
            const u64 px = pack2(p0[gg].x, p0[gg].x);
            const u64 py = pack2(p0[gg].y, p0[gg].y);
            const u64 pz = pack2(p1[gg].x, p1[gg].x);
            const u64 pw = pack2(p1[gg].y, p1[gg].y);

            float th0, th1, th2, th3;
            {
                u64 tp0 = fma2(px, wA[0], fma2(py, wB[0], fma2(pz, wC[0], fma2(pw, wD[0], bbp[0]))));
                u64 tp1 = fma2(px, wA[1], fma2(py, wB[1], fma2(pz, wC[1], fma2(pw, wD[1], bbp[1]))));
                unpack2(tp0, th0, th1);
                unpack2(tp1, th2, th3);
            }

            float s0, c0, s1, c1;
            __sincosf(th0, &s0, &c0);
            __sincosf(th1, &s1, &c1);
            const float c2 = __cosf(th2);
            const float c3 = __cosf(th3);

            const float okf = (b0 + g < B) ? 1.0f : 0.0f;
            const float ez0 = okf * fmaf(ca4, c0, -sa4 * s0 * s1);
            const float ez1 = okf * (c0 * c1);
            const float ez2 = ez1 * c2;
            const float ez3 = ez2 * c3;

            const u64 e0 = pack2(ez0, ez0);
            const u64 e1 = pack2(ez1, ez1);
            const u64 e2 = pack2(ez2, ez2);
            const u64 e3 = pack2(ez3, ez3);

            u64 acc[NP];
#pragma unroll
            for (int j = 0; j < NP; j++)
                acc[j] = fma2(e0, fw2[0][j],
                         fma2(e1, fw2[1][j],
                         fma2(e2, fw2[2][j],
                         fma2(e3, fw2[3][j], zz))));

            // 1-level reduce (lane += lane+16), packed
#pragma unroll
            for (int j = 0; j < NP; j++) {
                u64 other = __shfl_down_sync(0xffffffffu, acc[j], 16);
                acc[j] = add2(acc[j], other);
            }
            if (lane < 16) {
#pragma unroll
                for (int j = 0; j < NP; j++)
                    s_part[warp][lane][g * NP + j] = acc[j];
            }
        }
    }

    // ---- 5) warp-0 epilogue: patches 192..195 x 7 images -> lanes 0..27 ----
    if (warp == 0) {
        __syncwarp();                   // s_fwx cross-lane visibility
        const int e  = lane & 3;        // extra patch 192+e -> (h=13, w=10+e)
        const int ge = lane >> 2;       // image index 0..7 (only <7 active)
        const int b  = b0 + ge;
        if (ge < G_IMGS) {
            u64 accx[NP];
            if (b < B) {
                const float* xb = x + (size_t)b * 784 + 26 * 28 + 2 * (10 + e);
                float2 q0 = *reinterpret_cast<const float2*>(xb);
                float2 q1 = *reinterpret_cast<const float2*>(xb + 28);

                const u64 px = pack2(q0.x, q0.x);
                const u64 py = pack2(q0.y, q0.y);
                const u64 pz = pack2(q1.x, q1.x);
                const u64 pw = pack2(q1.y, q1.y);

                float th0, th1, th2, th3;
                {
                    u64 tp0 = fma2(px, wA[0], fma2(py, wB[0], fma2(pz, wC[0], fma2(pw, wD[0], bbp[0]))));
                    u64 tp1 = fma2(px, wA[1], fma2(py, wB[1], fma2(pz, wC[1], fma2(pw, wD[1], bbp[1]))));
                    unpack2(tp0, th0, th1);
                    unpack2(tp1, th2, th3);
                }

                float s0, c0, s1, c1;
                __sincosf(th0, &s0, &c0);
                __sincosf(th1, &s1, &c1);
                const float c2 = __cosf(th2);
                const float c3 = __cosf(th3);

                const float ez0 = fmaf(ca4, c0, -sa4 * s0 * s1);
                const float ez1 = c0 * c1;
                const float ez2 = ez1 * c2;
                const float ez3 = ez2 * c3;

                const u64 e0p = pack2(ez0, ez0);
                const u64 e1p = pack2(ez1, ez1);
                const u64 e2p = pack2(ez2, ez2);
                const u64 e3p = pack2(ez3, ez3);
#pragma unroll
                for (int j = 0; j < NP; j++)
                    accx[j] = fma2(e0p, s_fwx[0][e][j],
                              fma2(e1p, s_fwx[1][e][j],
                              fma2(e2p, s_fwx[2][e][j],
                              fma2(e3p, s_fwx[3][e][j], zz))));
            } else {
#pragma unroll
                for (int j = 0; j < NP; j++) accx[j] = zz;
            }
#pragma unroll
            for (int j = 0; j < NP; j++)
                s_extra[ge][e][j] = accx[j];
        }
    }
    __syncthreads();

    // ---- 6) tail: one thread per (image, class-pair) sums 96 partials + extras ----
    if (t < G_IMGS * NP) {
        const int g = t / NP, j = t - g * NP;
        u64 v0 = pack2(fc_b[2 * j], fc_b[2 * j + 1]);
        u64 v1 = zz, v2 = zz, v3 = zz;
#pragma unroll
        for (int k = 0; k < NW; k++) {
#pragma unroll
            for (int i = 0; i < 16; i += 4) {
                v0 = add2(v0, s_part[k][i + 0][t]);
                v1 = add2(v1, s_part[k][i + 1][t]);
                v2 = add2(v2, s_part[k][i + 2][t]);
                v3 = add2(v3, s_part[k][i + 3][t]);
            }
        }
#pragma unroll
        for (int ee = 0; ee < 4; ee++)
            v0 = add2(v0, s_extra[g][ee][j]);
        u64 v = add2(add2(v0, v1), add2(v2, v3));
        float lo, hi; unpack2(v, lo, hi);
        s_logits[g][2 * j]     = lo;
        s_logits[g][2 * j + 1] = hi;
    }
    __syncthreads();

    // ---- 7) log_softmax over 10 classes ----
    if (t < G_IMGS * 10) {
        const int g = t / 10, o = t - g * 10;
        const int b = b0 + g;
        if (b < B) {
            float m = -1e30f;
#pragma unroll
            for (int j = 0; j < 10; j++) m = fmaxf(m, s_logits[g][j]);
            float se = 0.0f;
#pragma unroll
            for (int j = 0; j < 10; j++) se += __expf(s_logits[g][j] - m);
            out[b * 10 + o] = s_logits[g][o] - m - __logf(se);
        }
    }
}

extern "C" void kernel_launch(void* const* d_in, const int* in_sizes, int n_in,
                              void* d_out, int out_size)
{
    const float* x      = (const float*)d_in[0];
    const float* conv_w = (const float*)d_in[1];
    const float* conv_b = (const float*)d_in[2];
    const float* angles = (const float*)d_in[3];
    const float* fc_w   = (const float*)d_in[4];
    const float* fc_b   = (const float*)d_in[5];
    float* out = (float*)d_out;

    const int B = in_sizes[0] / 784;                 // 4096
    const int blocks = (B + G_IMGS - 1) / G_IMGS;    // 586

    quanv_fused<<<blocks, TPB>>>(x, conv_w, conv_b, angles, fc_w, fc_b, out, B);
}

// round 13
// speedup vs baseline: 1.2186x; 1.0030x over previous
#include <cuda_runtime.h>

// Fused Quanvolution-Hybrid (analytic 4-qubit circuit), f32x2, G=10 @ 3 blocks/SM.
//   theta_w = conv_out_w + angles[w];  c_w=cos, s_w=sin
//   <Z0> = cos(a4)*c0 - sin(a4)*s0*s1
//   <Z1> = c0*c1,  <Z2> = c0*c1*c2,  <Z3> = c0*c1*c2*c3
// Patches 0..191 -> threads 1:1. Patches 192..195 x 10 images -> warps 0-1 (40 lanes).

#define G_IMGS 10
#define TPB    192        // 6 warps, all fully active
#define NW     6
#define NP     5          // 10 classes as 5 packed pairs
#define PSTR   51         // 10*5 + 1 pad (odd stride -> conflict-free)

typedef unsigned long long u64;

__device__ __forceinline__ u64 pack2(float lo, float hi) {
    u64 r; asm("mov.b64 %0,{%1,%2};" : "=l"(r) : "f"(lo), "f"(hi)); return r;
}
__device__ __forceinline__ void unpack2(u64 v, float& lo, float& hi) {
    asm("mov.b64 {%0,%1},%2;" : "=f"(lo), "=f"(hi) : "l"(v));
}
__device__ __forceinline__ u64 fma2(u64 a, u64 b, u64 c) {
    u64 d; asm("fma.rn.f32x2 %0,%1,%2,%3;" : "=l"(d) : "l"(a), "l"(b), "l"(c)); return d;
}
__device__ __forceinline__ u64 add2(u64 a, u64 b) {
    u64 d; asm("add.rn.f32x2 %0,%1,%2;" : "=l"(d) : "l"(a), "l"(b)); return d;
}

__global__ __launch_bounds__(TPB, 3) void quanv_fused(
    const float* __restrict__ x,        // [B,1,28,28]
    const float* __restrict__ conv_w,   // [4,1,2,2]
    const float* __restrict__ conv_b,   // [4]
    const float* __restrict__ angles,   // [5]
    const float* __restrict__ fc_w,     // [10, 784]
    const float* __restrict__ fc_b,     // [10]
    float* __restrict__ out,            // [B,10]
    int B)
{
    const int t    = threadIdx.x;
    const int lane = t & 31;
    const int warp = t >> 5;
    const int b0   = blockIdx.x * G_IMGS;

    __shared__ u64   s_part[NW][16][PSTR];     // main partial logit pairs (~38 KB)
    __shared__ u64   s_extra[G_IMGS][4][NP];   // epilogue partials
    __shared__ u64   s_fwx[4][4][NP];          // fc weights for patches 192..195
    __shared__ float s_logits[G_IMGS][10];

    const int h    = t / 14;
    const int wq   = t - h * 14;
    const int poff = (2 * h) * 28 + 2 * wq;   // even -> 8B aligned float2

    // ---- 1) issue chunk-0 x loads first (4 images) ----
    float2 p0[4], p1[4];
#pragma unroll
    for (int gg = 0; gg < 4; gg++) {
        const int b = b0 + gg;
        if (b < B) {
            const float* xb = x + (size_t)b * 784 + poff;
            p0[gg] = *reinterpret_cast<const float2*>(xb);
            p1[gg] = *reinterpret_cast<const float2*>(xb + 28);
        } else {
            p0[gg] = make_float2(0.f, 0.f);
            p1[gg] = make_float2(0.f, 0.f);
        }
    }

    // ---- 2) uniform parameters; conv weights packed per channel pair ----
    u64 wA[2], wB[2], wC[2], wD[2], bbp[2];
#pragma unroll
    for (int c2 = 0; c2 < 2; c2++) {
        const int ca = 2 * c2, cb = 2 * c2 + 1;
        wA[c2]  = pack2(conv_w[ca * 4 + 0], conv_w[cb * 4 + 0]);
        wB[c2]  = pack2(conv_w[ca * 4 + 1], conv_w[cb * 4 + 1]);
        wC[c2]  = pack2(conv_w[ca * 4 + 2], conv_w[cb * 4 + 2]);
        wD[c2]  = pack2(conv_w[ca * 4 + 3], conv_w[cb * 4 + 3]);
        bbp[c2] = pack2(conv_b[ca] + angles[ca], conv_b[cb] + angles[cb]);
    }
    float sa4, ca4;
    __sincosf(angles[4], &sa4, &ca4);

    // ---- 3) per-thread FC weight slice (patch t), packed class pairs ----
    u64 fw2[4][NP];
#pragma unroll
    for (int c = 0; c < 4; c++) {
#pragma unroll
        for (int j = 0; j < NP; j++) {
            float lo = fc_w[(2 * j)     * 784 + c * 196 + t];
            float hi = fc_w[(2 * j + 1) * 784 + c * 196 + t];
            fw2[c][j] = pack2(lo, hi);
        }
    }

    // extra-patch FC weights -> shared, warp 0 fills (epilogue warps sync via barrier)
    if (warp == 0) {
        for (int r = lane; r < 80; r += 32) {
            const int c  = r / 20;
            const int rr = r - c * 20;
            const int ee = rr / NP;
            const int j  = rr - ee * NP;
            const int pe = 192 + ee;
            s_fwx[c][ee][j] = pack2(fc_w[(2 * j) * 784 + c * 196 + pe],
                                    fc_w[(2 * j + 1) * 784 + c * 196 + pe]);
        }
    }

    const u64 zz = pack2(0.0f, 0.0f);

    // ---- 4) main loop: chunks of (4,3,3) images ----
    const int csz[3]   = {4, 3, 3};
    const int cbase[3] = {0, 4, 7};
#pragma unroll
    for (int ch = 0; ch < 3; ch++) {
        if (ch > 0) {
#pragma unroll
            for (int gg = 0; gg < 3; gg++) {
                if (gg >= csz[ch]) break;
                const int b = b0 + cbase[ch] + gg;
                if (b < B) {
                    const float* xb = x + (size_t)b * 784 + poff;
                    p0[gg] = *reinterpret_cast<const float2*>(xb);
                    p1[gg] = *reinterpret_cast<const float2*>(xb + 28);
                } else {
                    p0[gg] = make_float2(0.f, 0.f);
                    p1[gg] = make_float2(0.f, 0.f);
                }
            }
        }

#pragma unroll
        for (int gg = 0; gg < 4; gg++) {
            if (gg >= csz[ch]) break;
            const int g = cbase[ch] + gg;

            // packed conv: theta pairs (ch 0,1) and (ch 2,3)
            const u64 px = pack2(p0[gg].x, p0[gg].x);
            const u64 py = pack2(p0[gg].y, p0[gg].y);
            const u64 pz = pack2(p1[gg].x, p1[gg].x);
            const u64 pw = pack2(p1[gg].y, p1[gg].y);

            float th0, th1, th2, th3;
            {
                u64 tp0 = fma2(px, wA[0], fma2(py, wB[0], fma2(pz, wC[0], fma2(pw, wD[0], bbp[0]))));
                u64 tp1 = fma2(px, wA[1], fma2(py, wB[1], fma2(pz, wC[1], fma2(pw, wD[1], bbp[1]))));
                unpack2(tp0, th0, th1);
                unpack2(tp1, th2, th3);
            }

            float s0, c0, s1, c1;
            __sincosf(th0, &s0, &c0);
            __sincosf(th1, &s1, &c1);
            const float c2 = __cosf(th2);
            const float c3 = __cosf(th3);

            const float okf = (b0 + g < B) ? 1.0f : 0.0f;
            const float ez0 = okf * fmaf(ca4, c0, -sa4 * s0 * s1);
            const float ez1 = okf * (c0 * c1);
            const float ez2 = ez1 * c2;
            const float ez3 = ez2 * c3;

            const u64 e0 = pack2(ez0, ez0);
            const u64 e1 = pack2(ez1, ez1);
            const u64 e2 = pack2(ez2, ez2);
            const u64 e3 = pack2(ez3, ez3);

            u64 acc[NP];
#pragma unroll
            for (int j = 0; j < NP; j++)
                acc[j] = fma2(e0, fw2[0][j],
                         fma2(e1, fw2[1][j],
                         fma2(e2, fw2[2][j],
                         fma2(e3, fw2[3][j], zz))));

            // 1-level reduce (lane += lane+16), packed
#pragma unroll
            for (int j = 0; j < NP; j++) {
                u64 other = __shfl_down_sync(0xffffffffu, acc[j], 16);
                acc[j] = add2(acc[j], other);
            }
            if (lane < 16) {
#pragma unroll
                for (int j = 0; j < NP; j++)
                    s_part[warp][lane][g * NP + j] = acc[j];
            }
        }
    }

    __syncthreads();   // s_fwx visible to warp 1; s_part complete

    // ---- 5) epilogue: patches 192..195 x 10 images -> warps 0-1 (40 instances) ----
    if (warp < 2) {
        const int idx = warp * 32 + lane;      // 0..63, active < 40
        const int e   = idx & 3;               // extra patch 192+e -> (h=13, w=10+e)
        const int ge  = idx >> 2;              // image index
        if (ge < G_IMGS) {
            const int b = b0 + ge;
            u64 accx[NP];
            if (b < B) {
                const float* xb = x + (size_t)b * 784 + 26 * 28 + 2 * (10 + e);
                float2 q0 = *reinterpret_cast<const float2*>(xb);
                float2 q1 = *reinterpret_cast<const float2*>(xb + 28);

                const u64 px = pack2(q0.x, q0.x);
                const u64 py = pack2(q0.y, q0.y);
                const u64 pz = pack2(q1.x, q1.x);
                const u64 pw = pack2(q1.y, q1.y);

                float th0, th1, th2, th3;
                {
                    u64 tp0 = fma2(px, wA[0], fma2(py, wB[0], fma2(pz, wC[0], fma2(pw, wD[0], bbp[0]))));
                    u64 tp1 = fma2(px, wA[1], fma2(py, wB[1], fma2(pz, wC[1], fma2(pw, wD[1], bbp[1]))));
                    unpack2(tp0, th0, th1);
                    unpack2(tp1, th2, th3);
                }

                float s0, c0, s1, c1;
                __sincosf(th0, &s0, &c0);
                __sincosf(th1, &s1, &c1);
                const float c2 = __cosf(th2);
                const float c3 = __cosf(th3);

                const float ez0 = fmaf(ca4, c0, -sa4 * s0 * s1);
                const float ez1 = c0 * c1;
                const float ez2 = ez1 * c2;
                const float ez3 = ez2 * c3;

                const u64 e0p = pack2(ez0, ez0);
                const u64 e1p = pack2(ez1, ez1);
                const u64 e2p = pack2(ez2, ez2);
                const u64 e3p = pack2(ez3, ez3);
#pragma unroll
                for (int j = 0; j < NP; j++)
                    accx[j] = fma2(e0p, s_fwx[0][e][j],
                              fma2(e1p, s_fwx[1][e][j],
                              fma2(e2p, s_fwx[2][e][j],
                              fma2(e3p, s_fwx[3][e][j], zz))));
            } else {
#pragma unroll
                for (int j = 0; j < NP; j++) accx[j] = zz;
            }
#pragma unroll
            for (int j = 0; j < NP; j++)
                s_extra[ge][e][j] = accx[j];
        }
    }
    __syncthreads();

    // ---- 6) tail: one thread per (image, class-pair) sums 96 partials + extras ----
    if (t < G_IMGS * NP) {
        const int g = t / NP, j = t - g * NP;
        u64 v0 = pack2(fc_b[2 * j], fc_b[2 * j + 1]);
        u64 v1 = zz, v2 = zz, v3 = zz;
#pragma unroll
        for (int k = 0; k < NW; k++) {
#pragma unroll
            for (int i = 0; i < 16; i += 4) {
                v0 = add2(v0, s_part[k][i + 0][t]);
                v1 = add2(v1, s_part[k][i + 1][t]);
                v2 = add2(v2, s_part[k][i + 2][t]);
                v3 = add2(v3, s_part[k][i + 3][t]);
            }
        }
#pragma unroll
        for (int ee = 0; ee < 4; ee++)
            v0 = add2(v0, s_extra[g][ee][j]);
        u64 v = add2(add2(v0, v1), add2(v2, v3));
        float lo, hi; unpack2(v, lo, hi);
        s_logits[g][2 * j]     = lo;
        s_logits[g][2 * j + 1] = hi;
    }
    __syncthreads();

    // ---- 7) log_softmax over 10 classes ----
    if (t < G_IMGS * 10) {
        const int g = t / 10, o = t - g * 10;
        const int b = b0 + g;
        if (b < B) {
            float m = -1e30f;
#pragma unroll
            for (int j = 0; j < 10; j++) m = fmaxf(m, s_logits[g][j]);
            float se = 0.0f;
#pragma unroll
            for (int j = 0; j < 10; j++) se += __expf(s_logits[g][j] - m);
            out[b * 10 + o] = s_logits[g][o] - m - __logf(se);
        }
    }
}

extern "C" void kernel_launch(void* const* d_in, const int* in_sizes, int n_in,
                              void* d_out, int out_size)
{
    const float* x      = (const float*)d_in[0];
    const float* conv_w = (const float*)d_in[1];
    const float* conv_b = (const float*)d_in[2];
    const float* angles = (const float*)d_in[3];
    const float* fc_w   = (const float*)d_in[4];
    const float* fc_b   = (const float*)d_in[5];
    float* out = (float*)d_out;

    const int B = in_sizes[0] / 784;                 // 4096
    const int blocks = (B + G_IMGS - 1) / G_IMGS;    // 410

    quanv_fused<<<blocks, TPB>>>(x, conv_w, conv_b, angles, fc_w, fc_b, out, B);
}